// round 3
// baseline (speedup 1.0000x reference)
#include <cuda_runtime.h>
#include <math.h>
#include <stdint.h>

#define NMAX 50000
#define DOUT 64
#define OSTRIDE 76
#define KCH 34            // 34 k-chunks of 8 -> K = 272 (265 real + 7 zero pad)
#define KP 276            // rad row stride in floats (bank-conflict-free)
#define WOP 72            // sW row stride in floats (bank-conflict-free)
#define TILE_E 128

// shared memory offsets (floats)
#define OFF_W 0                     // 272*72      = 19584
#define OFF_RAD 19584               // 128*276     = 35328
#define OFF_ATT 54912               // 8 warps*256 =  2048
#define OFF_M 56960                 // 8 warps*16  =   128
#define OFF_RINV 57088              // 128
#define OFF_ROW 57216               // 128
#define OFF_BIAS 57344              // 64
#define SMEM_FLOATS 57408           // *4 = 229632 bytes

__device__ float g_lf[NMAX * 9];
__device__ float g_pooled[NMAX * 3];
__device__ float g_cnt[NMAX];

// ---------------------------------------------------------------------------
__device__ __forceinline__ void red4(float* p, float a, float b, float c, float d) {
    asm volatile("red.global.add.v4.f32 [%0], {%1,%2,%3,%4};"
                 :: "l"(p), "f"(a), "f"(b), "f"(c), "f"(d) : "memory");
}

// ---------------------------------------------------------------------------
__global__ void zero_kernel(float* out, int out_n, int n_nodes) {
    int i = blockIdx.x * blockDim.x + threadIdx.x;
    int stride = gridDim.x * blockDim.x;
    for (int k = i; k < out_n; k += stride) out[k] = 0.f;
    for (int k = i; k < n_nodes; k += stride) g_cnt[k] = 0.f;
}

// ---------------------------------------------------------------------------
__global__ void node_kernel(const float* __restrict__ coord,
                            const float* __restrict__ cw, int n) {
    int v = blockIdx.x * blockDim.x + threadIdx.x;
    if (v >= n) return;
    const float* cp = coord + v * 12;
    float cax = cp[0], cay = cp[1], caz = cp[2];
    float ccx = cp[3], ccy = cp[4], ccz = cp[5];
    float nnx = cp[6], nny = cp[7], nnz = cp[8];

    float xx = ccx - cax, xy = ccy - cay, xz = ccz - caz;
    float xn = sqrtf(xx * xx + xy * xy + xz * xz) + 1e-8f;
    xx /= xn; xy /= xn; xz /= xn;

    float tx = nnx - cax, ty = nny - cay, tz = nnz - caz;
    float d = tx * xx + ty * xy + tz * xz;
    float yx = tx - d * xx, yy = ty - d * xy, yz = tz - d * xz;
    float yn = sqrtf(yx * yx + yy * yy + yz * yz) + 1e-8f;
    yx /= yn; yy /= yn; yz /= yn;

    float zx = xy * yz - xz * yy;
    float zy = xz * yx - xx * yz;
    float zz = xx * yy - xy * yx;

    float* L = g_lf + v * 9;
    L[0] = xx; L[1] = yx; L[2] = zx;
    L[3] = xy; L[4] = yy; L[5] = zy;
    L[6] = xz; L[7] = yz; L[8] = zz;

    float px = 0.f, py = 0.f, pz = 0.f, cs = 0.f;
#pragma unroll
    for (int i = 0; i < 4; i++) {
        float m = (cw[v * 4 + i] != 0.f) ? 1.f : 0.f;
        cs += m;
        px += cp[i * 3 + 0] * m;
        py += cp[i * 3 + 1] * m;
        pz += cp[i * 3 + 2] * m;
    }
    g_pooled[v * 3 + 0] = px / cs;
    g_pooled[v * 3 + 1] = py / cs;
    g_pooled[v * 3 + 2] = pz / cs;
}

// ---------------------------------------------------------------------------
__device__ __forceinline__ uint32_t f2tf(float f) {
    uint32_t u;
    asm("cvt.rna.tf32.f32 %0, %1;" : "=r"(u) : "f"(f));
    return u;
}

__device__ __forceinline__ void mma8(float& d0, float& d1, float& d2, float& d3,
                                     uint32_t a0, uint32_t a1, uint32_t a2, uint32_t a3,
                                     uint32_t b0, uint32_t b1) {
    asm volatile("mma.sync.aligned.m16n8k8.row.col.f32.tf32.tf32.f32 "
                 "{%0,%1,%2,%3}, {%4,%5,%6,%7}, {%8,%9}, {%0,%1,%2,%3};"
                 : "+f"(d0), "+f"(d1), "+f"(d2), "+f"(d3)
                 : "r"(a0), "r"(a1), "r"(a2), "r"(a3), "r"(b0), "r"(b1));
}

// Per-edge phase-1 body: build M via shuffles, compute radial + lf row of rad
// (tf32), fp32 norm -> rinv, coord-diff vector reductions.
__device__ __forceinline__ void process_edge(
    int lane, int b16, int half, int eloc, int r, int c, float gv, float lfv,
    bool valid, const float* s_ar, float* sMW, uint32_t* sRad, float* sRinv,
    float* out)
{
    int i = (lane >> 2) & 3, j = lane & 3;
    float rx = __shfl_sync(0xffffffffu, gv, 3 * i);
    float ry = __shfl_sync(0xffffffffu, gv, 3 * i + 1);
    float rz = __shfl_sync(0xffffffffu, gv, 3 * i + 2);
    float cx = __shfl_sync(0xffffffffu, gv, 12 + 3 * j);
    float cy = __shfl_sync(0xffffffffu, gv, 13 + 3 * j);
    float cz = __shfl_sync(0xffffffffu, gv, 14 + 3 * j);
    float wr = __shfl_sync(0xffffffffu, gv, 24 + i);
    float wc = __shfl_sync(0xffffffffu, gv, 28 + j);
    if (lane < 16) {
        float dx = rx - cx, dy = ry - cy, dz = rz - cz;
        sMW[lane] = sqrtf(dx * dx + dy * dy + dz * dz) * wr * wc;
    }
    __syncwarp();

    const float* s_ac = s_ar + 64;
    float a0 = s_ac[b16], a1 = s_ac[16 + b16], a2 = s_ac[32 + b16], a3 = s_ac[48 + b16];
    float tmp0 = sMW[0]  * a0 + sMW[1]  * a1 + sMW[2]  * a2 + sMW[3]  * a3;
    float tmp1 = sMW[4]  * a0 + sMW[5]  * a1 + sMW[6]  * a2 + sMW[7]  * a3;
    float tmp2 = sMW[8]  * a0 + sMW[9]  * a1 + sMW[10] * a2 + sMW[11] * a3;
    float tmp3 = sMW[12] * a0 + sMW[13] * a1 + sMW[14] * a2 + sMW[15] * a3;

    uint32_t* rrow = sRad + eloc * KP;
    float ssq = 0.f;
#pragma unroll
    for (int s = 0; s < 8; s++) {
        int a = half * 8 + s;
        float v = s_ar[a] * tmp0 + s_ar[16 + a] * tmp1
                + s_ar[32 + a] * tmp2 + s_ar[48 + a] * tmp3;
        rrow[a * 16 + b16] = f2tf(v);
        ssq += v * v;
    }
    if (lane < 9) {
        rrow[256 + lane] = f2tf(lfv);
        ssq += lfv * lfv;
    } else if (lane < 20) {
        rrow[256 + lane] = 0u;   // k = 265..275 zero pad
    }
#pragma unroll
    for (int off = 16; off; off >>= 1)
        ssq += __shfl_xor_sync(0xffffffffu, ssq, off);
    if (lane == 0) sRinv[eloc] = 1.f / (sqrtf(ssq) + 1.f);

    // coord aggregation: pack the 12 diffs into 3 lanes -> 3 RED.128 + 1 cnt
    float dco = 0.f;
    if (lane < 12) dco = gv - g_pooled[c * 3 + lane % 3];
    float q0 = __shfl_sync(0xffffffffu, dco, 4 * lane);
    float q1 = __shfl_sync(0xffffffffu, dco, 4 * lane + 1);
    float q2 = __shfl_sync(0xffffffffu, dco, 4 * lane + 2);
    float q3 = __shfl_sync(0xffffffffu, dco, 4 * lane + 3);
    if (valid) {
        if (lane < 3) red4(out + r * OSTRIDE + 64 + 4 * lane, q0, q1, q2, q3);
        else if (lane == 3) atomicAdd(&g_cnt[r], 1.f);
    }
    __syncwarp();
}

// ---------------------------------------------------------------------------
__global__ void __launch_bounds__(256, 1)
edge_kernel(const float* __restrict__ coord, const float* __restrict__ attr,
            const float* __restrict__ cw, const float* __restrict__ W,
            const float* __restrict__ bias, const int* __restrict__ row,
            const int* __restrict__ col, float* __restrict__ out, int E) {
    extern __shared__ float sm[];
    uint32_t* sW   = (uint32_t*)(sm + OFF_W);
    uint32_t* sRad = (uint32_t*)(sm + OFF_RAD);
    float* sAtt  = sm + OFF_ATT;
    float* sM    = sm + OFF_M;
    float* sRinv = sm + OFF_RINV;
    int*   sRow  = (int*)(sm + OFF_ROW);
    float* sBias = sm + OFF_BIAS;

    int tid = threadIdx.x, warp = tid >> 5, lane = tid & 31;

    // Stage W (tf32, transposed, geo-zero columns dropped) + bias. Once per CTA.
    for (int idx = tid; idx < 272 * 64; idx += 256) {
        int k = idx >> 6, o = idx & 63;
        float v = 0.f;
        if (k < 265) v = W[o * 273 + (k < 256 ? k : k + 8)];
        sW[k * WOP + o] = f2tf(v);
    }
    if (tid < 64) sBias[tid] = bias[tid];
    __syncthreads();

    const int g = lane >> 2, tig = lane & 3;
    const int b16 = lane & 15, half = lane >> 4;
    const int eh = (warp & 3) * 32;   // GEMM edge base (local)
    const int oh = (warp >> 2) * 32;  // GEMM output base
    float* sAttW = sAtt + warp * 256;
    float* sMW = sM + warp * 16;

    int ntile = (E + TILE_E - 1) / TILE_E;
    for (int tile = blockIdx.x; tile < ntile; tile += gridDim.x) {
        // ================= phase 1: build rad[128][276] =================
        int e0g = tile * TILE_E + warp * 16;
        int rc = 0;
        {
            int e = e0g + (lane & 15);
            if (e < E) rc = (lane < 16) ? row[e] : col[e];
        }
        if (lane < 16) sRow[warp * 16 + lane] = rc;

        for (int t = 0; t < 16; t += 2) {
            int r0 = __shfl_sync(0xffffffffu, rc, t);
            int c0 = __shfl_sync(0xffffffffu, rc, 16 + t);
            int r1 = __shfl_sync(0xffffffffu, rc, t + 1);
            int c1 = __shfl_sync(0xffffffffu, rc, 17 + t);

            int n0 = (lane < 16) ? r0 : c0;
            int n1 = (lane < 16) ? r1 : c1;
            float4 av0 = __ldg((const float4*)(attr + n0 * 64) + b16);
            float4 av1 = __ldg((const float4*)(attr + n1 * 64) + b16);

            auto gaddr = [&](int r, int c) -> const float* {
                if (lane < 12) return coord + r * 12 + lane;
                if (lane < 24) return coord + c * 12 + (lane - 12);
                if (lane < 28) return cw + r * 4 + (lane - 24);
                return cw + c * 4 + (lane - 28);
            };
            float gv0 = __ldg(gaddr(r0, c0));
            float gv1 = __ldg(gaddr(r1, c1));

            float lf0 = 0.f, lf1 = 0.f;
            if (lane < 9) {
                lf0 = g_lf[r0 * 9 + lane] + g_lf[c0 * 9 + lane];
                lf1 = g_lf[r1 * 9 + lane] + g_lf[c1 * 9 + lane];
            }

            ((float4*)sAttW)[lane] = av0;        // slot 0: [attr_r | attr_c]
            ((float4*)sAttW)[32 + lane] = av1;   // slot 1
            __syncwarp();

            process_edge(lane, b16, half, warp * 16 + t, r0, c0, gv0, lf0,
                         (e0g + t) < E, sAttW, sMW, sRad, sRinv, out);
            process_edge(lane, b16, half, warp * 16 + t + 1, r1, c1, gv1, lf1,
                         (e0g + t + 1) < E, sAttW + 128, sMW, sRad, sRinv, out);
        }
        __syncthreads();

        // ================= phase 2: tf32 MMA, 32 edges x 32 outs per warp ====
        float acc[2][4][4];
#pragma unroll
        for (int m = 0; m < 2; m++)
#pragma unroll
            for (int n = 0; n < 4; n++)
#pragma unroll
                for (int q = 0; q < 4; q++) acc[m][n][q] = 0.f;

        const uint32_t* aB0 = sRad + (eh + g) * KP + tig;
        const uint32_t* aB1 = sRad + (eh + 16 + g) * KP + tig;
        const uint32_t* bB  = sW + tig * WOP + oh + g;

#pragma unroll 2
        for (int kc = 0; kc < KCH; kc++) {
            int k0 = kc * 8;
            uint32_t A[2][4];
            A[0][0] = aB0[k0];
            A[0][1] = aB0[8 * KP + k0];
            A[0][2] = aB0[k0 + 4];
            A[0][3] = aB0[8 * KP + k0 + 4];
            A[1][0] = aB1[k0];
            A[1][1] = aB1[8 * KP + k0];
            A[1][2] = aB1[k0 + 4];
            A[1][3] = aB1[8 * KP + k0 + 4];
            uint32_t B[4][2];
#pragma unroll
            for (int n = 0; n < 4; n++) {
                B[n][0] = bB[k0 * WOP + n * 8];
                B[n][1] = bB[(k0 + 4) * WOP + n * 8];
            }
#pragma unroll
            for (int m = 0; m < 2; m++)
#pragma unroll
                for (int n = 0; n < 4; n++)
                    mma8(acc[m][n][0], acc[m][n][1], acc[m][n][2], acc[m][n][3],
                         A[m][0], A[m][1], A[m][2], A[m][3], B[n][0], B[n][1]);
        }

        // ========== epilogue: (acc + b) * rinv -> vectorized RED.128 =========
        // Lane pair (xor 1) assembles 4 contiguous outputs; each lane emits
        // 8 red.v4 per tile instead of 32 scalar atomics.
#pragma unroll
        for (int m = 0; m < 2; m++) {
#pragma unroll
            for (int h = 0; h < 2; h++) {
                int el = eh + m * 16 + h * 8 + g;
                bool valid = (tile * TILE_E + el) < E;
                float ri = sRinv[el];
                float* ob = out + sRow[el] * OSTRIDE;
                float vx[4], vy[4], ox[4], oy[4];
#pragma unroll
                for (int n = 0; n < 4; n++) {
                    int c0 = oh + n * 8 + 2 * tig;
                    vx[n] = (acc[m][n][2 * h]     + sBias[c0])     * ri;
                    vy[n] = (acc[m][n][2 * h + 1] + sBias[c0 + 1]) * ri;
                }
#pragma unroll
                for (int n = 0; n < 4; n++) {
                    ox[n] = __shfl_xor_sync(0xffffffffu, vx[n], 1);
                    oy[n] = __shfl_xor_sync(0xffffffffu, vy[n], 1);
                }
                int nb = tig & 1;            // which n-blocks this lane emits
                int cb = (tig >> 1) ? 4 : 0; // low/high 4 of the 8-col block
                bool ownfirst = !(tig & 1);
#pragma unroll
                for (int s = 0; s < 2; s++) {
                    int n = nb + 2 * s;
                    float e0, e1, e2, e3;
                    if (ownfirst) { e0 = vx[n]; e1 = vy[n]; e2 = ox[n]; e3 = oy[n]; }
                    else          { e0 = ox[n]; e1 = oy[n]; e2 = vx[n]; e3 = vy[n]; }
                    if (valid) red4(ob + oh + n * 8 + cb, e0, e1, e2, e3);
                }
            }
        }
        __syncthreads();   // protect rad/rinv/row before next tile's phase 1
    }
}

// ---------------------------------------------------------------------------
__global__ void finalize_kernel(float* out, int n) {
    int v = blockIdx.x * blockDim.x + threadIdx.x;
    if (v >= n) return;
    float cf = 1.f / fmaxf(g_cnt[v], 1.f);
    float* p = out + v * OSTRIDE + 64;
#pragma unroll
    for (int d = 0; d < 12; d++) p[d] *= cf;
}

// ---------------------------------------------------------------------------
extern "C" void kernel_launch(void* const* d_in, const int* in_sizes, int n_in,
                              void* d_out, int out_size) {
    const float* coord = (const float*)d_in[0];
    const float* attr  = (const float*)d_in[1];
    const float* cw    = (const float*)d_in[2];
    const float* W     = (const float*)d_in[3];
    const float* bias  = (const float*)d_in[4];
    const int*   row   = (const int*)d_in[5];
    const int*   col   = (const int*)d_in[6];
    float* out = (float*)d_out;

    int N = in_sizes[2] / 4;
    int E = in_sizes[5];

    int smem_bytes = SMEM_FLOATS * sizeof(float);   // 229632
    cudaFuncSetAttribute(edge_kernel, cudaFuncAttributeMaxDynamicSharedMemorySize,
                         smem_bytes);

    zero_kernel<<<512, 256>>>(out, out_size, N);
    node_kernel<<<(N + 255) / 256, 256>>>(coord, cw, N);
    edge_kernel<<<148, 256, smem_bytes>>>(coord, attr, cw, W, bias, row, col, out, E);
    finalize_kernel<<<(N + 255) / 256, 256>>>(out, N);
}

// round 4
// speedup vs baseline: 1.4435x; 1.4435x over previous
#include <cuda_runtime.h>
#include <math.h>
#include <stdint.h>

#define NMAX 50000
#define DOUT 64
#define OSTRIDE 76
#define KCH 34            // 34 k-chunks of 8 -> K = 272 (265 real + 7 zero pad)
#define KP 276            // rad row stride (bank-conflict-free: 276 % 32 = 20)
#define WOP 72            // sW row stride (bank-conflict-free)
#define TILE_E 128
#define NWARP 16

// shared memory offsets (floats)
#define OFF_W 0                     // 272*72       = 19584
#define OFF_RAD 19584               // 128*276      = 35328 -> 54912
#define OFF_ATT 54912               // 16 warps*128 =  2048 -> 56960
#define OFF_M 56960                 // 16 warps*16  =   256 -> 57216
#define OFF_RINV 57216              // 128 -> 57344
#define OFF_ROW 57344               // 128 -> 57472
#define OFF_BIAS 57472              // 64  -> 57536
#define SMEM_FLOATS 57536           // *4 = 230144 bytes (< 227KB limit)

__device__ float g_lf[NMAX * 9];
__device__ float g_pooled[NMAX * 3];
__device__ float g_cnt[NMAX];

// ---------------------------------------------------------------------------
__global__ void zero_kernel(float* out, int out_n, int n_nodes) {
    int i = blockIdx.x * blockDim.x + threadIdx.x;
    int stride = gridDim.x * blockDim.x;
    for (int k = i; k < out_n; k += stride) out[k] = 0.f;
    for (int k = i; k < n_nodes; k += stride) g_cnt[k] = 0.f;
}

// ---------------------------------------------------------------------------
__global__ void node_kernel(const float* __restrict__ coord,
                            const float* __restrict__ cw, int n) {
    int v = blockIdx.x * blockDim.x + threadIdx.x;
    if (v >= n) return;
    const float* cp = coord + v * 12;
    float cax = cp[0], cay = cp[1], caz = cp[2];
    float ccx = cp[3], ccy = cp[4], ccz = cp[5];
    float nnx = cp[6], nny = cp[7], nnz = cp[8];

    float xx = ccx - cax, xy = ccy - cay, xz = ccz - caz;
    float xn = sqrtf(xx * xx + xy * xy + xz * xz) + 1e-8f;
    xx /= xn; xy /= xn; xz /= xn;

    float tx = nnx - cax, ty = nny - cay, tz = nnz - caz;
    float d = tx * xx + ty * xy + tz * xz;
    float yx = tx - d * xx, yy = ty - d * xy, yz = tz - d * xz;
    float yn = sqrtf(yx * yx + yy * yy + yz * yz) + 1e-8f;
    yx /= yn; yy /= yn; yz /= yn;

    float zx = xy * yz - xz * yy;
    float zy = xz * yx - xx * yz;
    float zz = xx * yy - xy * yx;

    float* L = g_lf + v * 9;
    L[0] = xx; L[1] = yx; L[2] = zx;
    L[3] = xy; L[4] = yy; L[5] = zy;
    L[6] = xz; L[7] = yz; L[8] = zz;

    float px = 0.f, py = 0.f, pz = 0.f, cs = 0.f;
#pragma unroll
    for (int i = 0; i < 4; i++) {
        float m = (cw[v * 4 + i] != 0.f) ? 1.f : 0.f;
        cs += m;
        px += cp[i * 3 + 0] * m;
        py += cp[i * 3 + 1] * m;
        pz += cp[i * 3 + 2] * m;
    }
    g_pooled[v * 3 + 0] = px / cs;
    g_pooled[v * 3 + 1] = py / cs;
    g_pooled[v * 3 + 2] = pz / cs;
}

// ---------------------------------------------------------------------------
__device__ __forceinline__ uint32_t f2tf(float f) {
    uint32_t u;
    asm("cvt.rna.tf32.f32 %0, %1;" : "=r"(u) : "f"(f));
    return u;
}

__device__ __forceinline__ void mma8(float& d0, float& d1, float& d2, float& d3,
                                     uint32_t a0, uint32_t a1, uint32_t a2, uint32_t a3,
                                     uint32_t b0, uint32_t b1) {
    asm volatile("mma.sync.aligned.m16n8k8.row.col.f32.tf32.tf32.f32 "
                 "{%0,%1,%2,%3}, {%4,%5,%6,%7}, {%8,%9}, {%0,%1,%2,%3};"
                 : "+f"(d0), "+f"(d1), "+f"(d2), "+f"(d3)
                 : "r"(a0), "r"(a1), "r"(a2), "r"(a3), "r"(b0), "r"(b1));
}

// ---------------------------------------------------------------------------
__global__ void __launch_bounds__(512, 1)
edge_kernel(const float* __restrict__ coord, const float* __restrict__ attr,
            const float* __restrict__ cw, const float* __restrict__ W,
            const float* __restrict__ bias, const int* __restrict__ row,
            const int* __restrict__ col, float* __restrict__ out, int E) {
    extern __shared__ float sm[];
    uint32_t* sW   = (uint32_t*)(sm + OFF_W);
    uint32_t* sRad = (uint32_t*)(sm + OFF_RAD);
    float* sAtt  = sm + OFF_ATT;
    float* sM    = sm + OFF_M;
    float* sRinv = sm + OFF_RINV;
    int*   sRow  = (int*)(sm + OFF_ROW);
    float* sBias = sm + OFF_BIAS;

    int tid = threadIdx.x, warp = tid >> 5, lane = tid & 31;

    // Stage W (tf32, transposed, geo-zero columns dropped) + bias. Once per CTA.
    for (int idx = tid; idx < 272 * 64; idx += 512) {
        int k = idx >> 6, o = idx & 63;
        float v = 0.f;
        if (k < 265) v = W[o * 273 + (k < 256 ? k : k + 8)];
        sW[k * WOP + o] = f2tf(v);
    }
    if (tid < 64) sBias[tid] = bias[tid];
    __syncthreads();

    const int g = lane >> 2, tig = lane & 3;
    const int b16 = lane & 15, half = lane >> 4;
    const int eh = (warp & 7) * 16;   // GEMM edge base (local) : 8 edge blocks
    const int oh = (warp >> 3) * 32;  // GEMM output base       : 2 col halves
    float* sAttW = sAtt + warp * 128;   // [attr_r(64) | attr_c(64)]
    float* sMW = sM + warp * 16;
    const int mi = (lane >> 2) & 3, mj = lane & 3;

    int ntile = (E + TILE_E - 1) / TILE_E;
    for (int tile = blockIdx.x; tile < ntile; tile += gridDim.x) {
        // ================= phase 1: 8 edges per warp =================
        int e0g = tile * TILE_E + warp * 8;
        int rc = 0;
        {
            int e = e0g + (lane & 7);
            if (e < E) rc = (lane < 16) ? row[e] : col[e];
        }
        if (lane < 8) sRow[warp * 8 + lane] = rc;

        float ssq[8];
#pragma unroll
        for (int t = 0; t < 8; t++) {
            int r = __shfl_sync(0xffffffffu, rc, t);
            int c = __shfl_sync(0xffffffffu, rc, 16 + t);

            int nn = (lane < 16) ? r : c;
            float4 av = __ldg((const float4*)(attr + nn * 64) + b16);

            const float* gp;
            if (lane < 12)      gp = coord + r * 12 + lane;
            else if (lane < 24) gp = coord + c * 12 + (lane - 12);
            else if (lane < 28) gp = cw + r * 4 + (lane - 24);
            else                gp = cw + c * 4 + (lane - 28);
            float gv = __ldg(gp);

            float lfv = 0.f;
            if (lane < 9) lfv = g_lf[r * 9 + lane] + g_lf[c * 9 + lane];

            ((float4*)sAttW)[lane] = av;

            float rx = __shfl_sync(0xffffffffu, gv, 3 * mi);
            float ry = __shfl_sync(0xffffffffu, gv, 3 * mi + 1);
            float rz = __shfl_sync(0xffffffffu, gv, 3 * mi + 2);
            float cx = __shfl_sync(0xffffffffu, gv, 12 + 3 * mj);
            float cy = __shfl_sync(0xffffffffu, gv, 13 + 3 * mj);
            float cz = __shfl_sync(0xffffffffu, gv, 14 + 3 * mj);
            float wr = __shfl_sync(0xffffffffu, gv, 24 + mi);
            float wc = __shfl_sync(0xffffffffu, gv, 28 + mj);
            if (lane < 16) {
                float dx = rx - cx, dy = ry - cy, dz = rz - cz;
                sMW[lane] = sqrtf(dx * dx + dy * dy + dz * dz) * wr * wc;
            }
            __syncwarp();

            const float* s_ac = sAttW + 64;
            float a0 = s_ac[b16], a1 = s_ac[16 + b16];
            float a2 = s_ac[32 + b16], a3 = s_ac[48 + b16];
            float tmp0 = sMW[0]  * a0 + sMW[1]  * a1 + sMW[2]  * a2 + sMW[3]  * a3;
            float tmp1 = sMW[4]  * a0 + sMW[5]  * a1 + sMW[6]  * a2 + sMW[7]  * a3;
            float tmp2 = sMW[8]  * a0 + sMW[9]  * a1 + sMW[10] * a2 + sMW[11] * a3;
            float tmp3 = sMW[12] * a0 + sMW[13] * a1 + sMW[14] * a2 + sMW[15] * a3;

            uint32_t* rrow = sRad + (warp * 8 + t) * KP;
            float part = 0.f;
#pragma unroll
            for (int s = 0; s < 8; s++) {
                int a = half * 8 + s;
                float v = sAttW[a] * tmp0 + sAttW[16 + a] * tmp1
                        + sAttW[32 + a] * tmp2 + sAttW[48 + a] * tmp3;
                rrow[a * 16 + b16] = f2tf(v);
                part += v * v;
            }
            if (lane < 9) {
                rrow[256 + lane] = f2tf(lfv);
                part += lfv * lfv;
            } else if (lane < 20) {
                rrow[256 + lane] = 0u;   // k = 265..275 zero pad
            }
            ssq[t] = part;

            // coord aggregation + count (fire-and-forget REDG)
            if (e0g + t < E) {
                if (lane < 12)
                    atomicAdd(out + r * OSTRIDE + 64 + lane,
                              gv - g_pooled[c * 3 + lane % 3]);
                else if (lane == 12)
                    atomicAdd(&g_cnt[r], 1.f);
            }
            __syncwarp();
        }

        // deferred reductions: 8 independent shuffle trees, pipelined
#pragma unroll
        for (int t = 0; t < 8; t++) {
            float s = ssq[t];
            s += __shfl_xor_sync(0xffffffffu, s, 16);
            s += __shfl_xor_sync(0xffffffffu, s, 8);
            s += __shfl_xor_sync(0xffffffffu, s, 4);
            s += __shfl_xor_sync(0xffffffffu, s, 2);
            s += __shfl_xor_sync(0xffffffffu, s, 1);
            if (lane == t) sRinv[warp * 8 + t] = __frcp_rn(sqrtf(s) + 1.f);
        }
        __syncthreads();

        // ============ phase 2: tf32 MMA, 16 edges x 32 outs per warp ========
        float acc[4][4];
#pragma unroll
        for (int n = 0; n < 4; n++)
#pragma unroll
            for (int q = 0; q < 4; q++) acc[n][q] = 0.f;

        const uint32_t* aB = sRad + (eh + g) * KP + tig;
        const uint32_t* bB = sW + tig * WOP + oh + g;

#pragma unroll 2
        for (int kc = 0; kc < KCH; kc++) {
            int k0 = kc * 8;
            uint32_t A0 = aB[k0];
            uint32_t A1 = aB[8 * KP + k0];
            uint32_t A2 = aB[k0 + 4];
            uint32_t A3 = aB[8 * KP + k0 + 4];
            uint32_t B[4][2];
#pragma unroll
            for (int n = 0; n < 4; n++) {
                B[n][0] = bB[k0 * WOP + n * 8];
                B[n][1] = bB[(k0 + 4) * WOP + n * 8];
            }
#pragma unroll
            for (int n = 0; n < 4; n++)
                mma8(acc[n][0], acc[n][1], acc[n][2], acc[n][3],
                     A0, A1, A2, A3, B[n][0], B[n][1]);
        }

        // ============ epilogue: (acc + b) * rinv -> scalar atomics ==========
        {
            int el0 = eh + g, el1 = eh + 8 + g;
            bool v0 = (tile * TILE_E + el0) < E;
            bool v1 = (tile * TILE_E + el1) < E;
            float ri0 = sRinv[el0], ri1 = sRinv[el1];
            float* ob0 = out + sRow[el0] * OSTRIDE;
            float* ob1 = out + sRow[el1] * OSTRIDE;
#pragma unroll
            for (int n = 0; n < 4; n++) {
                int o = oh + n * 8 + 2 * tig;
                float bo0 = sBias[o], bo1 = sBias[o + 1];
                if (v0) {
                    atomicAdd(ob0 + o,     (acc[n][0] + bo0) * ri0);
                    atomicAdd(ob0 + o + 1, (acc[n][1] + bo1) * ri0);
                }
                if (v1) {
                    atomicAdd(ob1 + o,     (acc[n][2] + bo0) * ri1);
                    atomicAdd(ob1 + o + 1, (acc[n][3] + bo1) * ri1);
                }
            }
        }
        __syncthreads();   // protect rad/rinv/row before next tile's phase 1
    }
}

// ---------------------------------------------------------------------------
__global__ void finalize_kernel(float* out, int n) {
    int v = blockIdx.x * blockDim.x + threadIdx.x;
    if (v >= n) return;
    float cf = 1.f / fmaxf(g_cnt[v], 1.f);
    float* p = out + v * OSTRIDE + 64;
#pragma unroll
    for (int d = 0; d < 12; d++) p[d] *= cf;
}

// ---------------------------------------------------------------------------
extern "C" void kernel_launch(void* const* d_in, const int* in_sizes, int n_in,
                              void* d_out, int out_size) {
    const float* coord = (const float*)d_in[0];
    const float* attr  = (const float*)d_in[1];
    const float* cw    = (const float*)d_in[2];
    const float* W     = (const float*)d_in[3];
    const float* bias  = (const float*)d_in[4];
    const int*   row   = (const int*)d_in[5];
    const int*   col   = (const int*)d_in[6];
    float* out = (float*)d_out;

    int N = in_sizes[2] / 4;
    int E = in_sizes[5];

    int smem_bytes = SMEM_FLOATS * sizeof(float);   // 230144
    cudaFuncSetAttribute(edge_kernel, cudaFuncAttributeMaxDynamicSharedMemorySize,
                         smem_bytes);

    zero_kernel<<<512, 256>>>(out, out_size, N);
    node_kernel<<<(N + 255) / 256, 256>>>(coord, cw, N);
    edge_kernel<<<148, 512, smem_bytes>>>(coord, attr, cw, W, bias, row, col, out, E);
    finalize_kernel<<<(N + 255) / 256, 256>>>(out, N);
}

// round 5
// speedup vs baseline: 1.5584x; 1.0796x over previous
#include <cuda_runtime.h>
#include <math.h>
#include <stdint.h>

#define NMAX 50000
#define DOUT 64
#define OSTRIDE 76
#define KCH 34            // 34 k-chunks of 8 -> K = 272 (265 real + 7 zero pad)
#define KP 276            // rad row stride (bank-conflict-free: 276 % 32 = 20)
#define WOP 72            // sW row stride (bank-conflict-free)
#define TILE_E 128
#define NWARP 16

// shared memory offsets (floats)
#define OFF_W 0                     // 272*72       = 19584
#define OFF_RAD 19584               // 128*276      = 35328 -> 54912
#define OFF_ATT 54912               // 16 warps*128 =  2048 -> 56960
#define OFF_M 56960                 // 16 warps*16  =   256 -> 57216
#define OFF_RINV 57216              // 128 -> 57344
#define OFF_ROW 57344               // 128 -> 57472
#define OFF_BIAS 57472              // 64  -> 57536
#define SMEM_FLOATS 57536           // *4 = 230144 bytes (< 227KB limit)

__device__ float g_lf[NMAX * 9];
__device__ float g_pooled[NMAX * 3];
__device__ float g_cnt[NMAX];

// ---------------------------------------------------------------------------
__global__ void zero_kernel(float* out, int out_n, int n_nodes) {
    int i = blockIdx.x * blockDim.x + threadIdx.x;
    int stride = gridDim.x * blockDim.x;
    for (int k = i; k < out_n; k += stride) out[k] = 0.f;
    for (int k = i; k < n_nodes; k += stride) g_cnt[k] = 0.f;
}

// ---------------------------------------------------------------------------
__global__ void node_kernel(const float* __restrict__ coord,
                            const float* __restrict__ cw, int n) {
    int v = blockIdx.x * blockDim.x + threadIdx.x;
    if (v >= n) return;
    const float* cp = coord + v * 12;
    float cax = cp[0], cay = cp[1], caz = cp[2];
    float ccx = cp[3], ccy = cp[4], ccz = cp[5];
    float nnx = cp[6], nny = cp[7], nnz = cp[8];

    float xx = ccx - cax, xy = ccy - cay, xz = ccz - caz;
    float xn = sqrtf(xx * xx + xy * xy + xz * xz) + 1e-8f;
    xx /= xn; xy /= xn; xz /= xn;

    float tx = nnx - cax, ty = nny - cay, tz = nnz - caz;
    float d = tx * xx + ty * xy + tz * xz;
    float yx = tx - d * xx, yy = ty - d * xy, yz = tz - d * xz;
    float yn = sqrtf(yx * yx + yy * yy + yz * yz) + 1e-8f;
    yx /= yn; yy /= yn; yz /= yn;

    float zx = xy * yz - xz * yy;
    float zy = xz * yx - xx * yz;
    float zz = xx * yy - xy * yx;

    float* L = g_lf + v * 9;
    L[0] = xx; L[1] = yx; L[2] = zx;
    L[3] = xy; L[4] = yy; L[5] = zy;
    L[6] = xz; L[7] = yz; L[8] = zz;

    float px = 0.f, py = 0.f, pz = 0.f, cs = 0.f;
#pragma unroll
    for (int i = 0; i < 4; i++) {
        float m = (cw[v * 4 + i] != 0.f) ? 1.f : 0.f;
        cs += m;
        px += cp[i * 3 + 0] * m;
        py += cp[i * 3 + 1] * m;
        pz += cp[i * 3 + 2] * m;
    }
    g_pooled[v * 3 + 0] = px / cs;
    g_pooled[v * 3 + 1] = py / cs;
    g_pooled[v * 3 + 2] = pz / cs;
}

// ---------------------------------------------------------------------------
__device__ __forceinline__ uint32_t f2tf(float f) {
    uint32_t u;
    asm("cvt.rna.tf32.f32 %0, %1;" : "=r"(u) : "f"(f));
    return u;
}

__device__ __forceinline__ void mma8(float& d0, float& d1, float& d2, float& d3,
                                     uint32_t a0, uint32_t a1, uint32_t a2, uint32_t a3,
                                     uint32_t b0, uint32_t b1) {
    asm volatile("mma.sync.aligned.m16n8k8.row.col.f32.tf32.tf32.f32 "
                 "{%0,%1,%2,%3}, {%4,%5,%6,%7}, {%8,%9}, {%0,%1,%2,%3};"
                 : "+f"(d0), "+f"(d1), "+f"(d2), "+f"(d3)
                 : "r"(a0), "r"(a1), "r"(a2), "r"(a3), "r"(b0), "r"(b1));
}

// ---------------------------------------------------------------------------
__global__ void __launch_bounds__(512, 1)
edge_kernel(const float* __restrict__ coord, const float* __restrict__ attr,
            const float* __restrict__ cw, const float* __restrict__ W,
            const float* __restrict__ bias, const int* __restrict__ row,
            const int* __restrict__ col, float* __restrict__ out, int E) {
    extern __shared__ float sm[];
    uint32_t* sW   = (uint32_t*)(sm + OFF_W);
    uint32_t* sRad = (uint32_t*)(sm + OFF_RAD);
    float* sAtt  = sm + OFF_ATT;
    float* sM    = sm + OFF_M;
    float* sRinv = sm + OFF_RINV;
    int*   sRow  = (int*)(sm + OFF_ROW);
    float* sBias = sm + OFF_BIAS;

    int tid = threadIdx.x, warp = tid >> 5, lane = tid & 31;

    // Stage W (tf32, transposed, geo-zero columns dropped) + bias. Once per CTA.
    for (int idx = tid; idx < 272 * 64; idx += 512) {
        int k = idx >> 6, o = idx & 63;
        float v = 0.f;
        if (k < 265) v = W[o * 273 + (k < 256 ? k : k + 8)];
        sW[k * WOP + o] = f2tf(v);
    }
    if (tid < 64) sBias[tid] = bias[tid];
    __syncthreads();

    const int g = lane >> 2, tig = lane & 3;
    const int b16 = lane & 15, half = lane >> 4;
    const int eh = (warp & 7) * 16;   // GEMM edge base (local) : 8 edge blocks
    const int oh = (warp >> 3) * 32;  // GEMM output base       : 2 col halves
    float* sAttW = sAtt + warp * 128;   // [attr_r(64) | attr_c(64)]
    float* sMW = sM + warp * 16;
    const int mi = (lane >> 2) & 3, mj = lane & 3;

    int ntile = (E + TILE_E - 1) / TILE_E;
    for (int tile = blockIdx.x; tile < ntile; tile += gridDim.x) {
        // ================= phase 1: 8 edges per warp =================
        int e0g = tile * TILE_E + warp * 8;
        int rc = 0;
        {
            int e = e0g + (lane & 7);
            if (e < E) rc = (lane < 16) ? row[e] : col[e];
        }
        if (lane < 8) sRow[warp * 8 + lane] = rc;

        float ssq[8];
#pragma unroll
        for (int h4 = 0; h4 < 2; h4++) {
            // ---- batched prefetch of 4 edges (MLP=4) ----
            float4 av[4];
            float gv[4], lfv[4], pv[4];
            int rr[4];
#pragma unroll
            for (int u = 0; u < 4; u++) {
                int t = h4 * 4 + u;
                int r = __shfl_sync(0xffffffffu, rc, t);
                int c = __shfl_sync(0xffffffffu, rc, 16 + t);
                rr[u] = r;
                int nn = (lane < 16) ? r : c;
                av[u] = __ldg((const float4*)(attr + nn * 64) + b16);
                const float* gp;
                if (lane < 12)      gp = coord + r * 12 + lane;
                else if (lane < 24) gp = coord + c * 12 + (lane - 12);
                else if (lane < 28) gp = cw + r * 4 + (lane - 24);
                else                gp = cw + c * 4 + (lane - 28);
                gv[u] = __ldg(gp);
                lfv[u] = (lane < 9)
                       ? g_lf[r * 9 + lane] + g_lf[c * 9 + lane] : 0.f;
                pv[u] = (lane < 12) ? g_pooled[c * 3 + lane % 3] : 0.f;
            }

            // ---- process the 4 edges ----
#pragma unroll
            for (int u = 0; u < 4; u++) {
                int t = h4 * 4 + u;
                ((float4*)sAttW)[lane] = av[u];

                float gvu = gv[u];
                float rx = __shfl_sync(0xffffffffu, gvu, 3 * mi);
                float ry = __shfl_sync(0xffffffffu, gvu, 3 * mi + 1);
                float rz = __shfl_sync(0xffffffffu, gvu, 3 * mi + 2);
                float cx = __shfl_sync(0xffffffffu, gvu, 12 + 3 * mj);
                float cy = __shfl_sync(0xffffffffu, gvu, 13 + 3 * mj);
                float cz = __shfl_sync(0xffffffffu, gvu, 14 + 3 * mj);
                float wr = __shfl_sync(0xffffffffu, gvu, 24 + mi);
                float wc = __shfl_sync(0xffffffffu, gvu, 28 + mj);
                if (lane < 16) {
                    float dx = rx - cx, dy = ry - cy, dz = rz - cz;
                    sMW[lane] = sqrtf(dx * dx + dy * dy + dz * dz) * wr * wc;
                }
                __syncwarp();

                const float* s_ac = sAttW + 64;
                float a0 = s_ac[b16], a1 = s_ac[16 + b16];
                float a2 = s_ac[32 + b16], a3 = s_ac[48 + b16];
                float tmp0 = sMW[0]  * a0 + sMW[1]  * a1 + sMW[2]  * a2 + sMW[3]  * a3;
                float tmp1 = sMW[4]  * a0 + sMW[5]  * a1 + sMW[6]  * a2 + sMW[7]  * a3;
                float tmp2 = sMW[8]  * a0 + sMW[9]  * a1 + sMW[10] * a2 + sMW[11] * a3;
                float tmp3 = sMW[12] * a0 + sMW[13] * a1 + sMW[14] * a2 + sMW[15] * a3;

                uint32_t* rrow = sRad + (warp * 8 + t) * KP;
                float part = 0.f;
#pragma unroll
                for (int s = 0; s < 8; s++) {
                    int a = half * 8 + s;
                    float v = sAttW[a] * tmp0 + sAttW[16 + a] * tmp1
                            + sAttW[32 + a] * tmp2 + sAttW[48 + a] * tmp3;
                    rrow[a * 16 + b16] = f2tf(v);
                    part += v * v;
                }
                if (lane < 9) {
                    rrow[256 + lane] = f2tf(lfv[u]);
                    part += lfv[u] * lfv[u];
                } else if (lane < 20) {
                    rrow[256 + lane] = 0u;   // k = 265..275 zero pad
                }
                ssq[t] = part;

                // coord aggregation + count (fire-and-forget REDG)
                if (e0g + t < E) {
                    if (lane < 12)
                        atomicAdd(out + rr[u] * OSTRIDE + 64 + lane, gvu - pv[u]);
                    else if (lane == 12)
                        atomicAdd(&g_cnt[rr[u]], 1.f);
                }
                __syncwarp();
            }
        }

        // deferred reductions: 8 independent shuffle trees, pipelined
#pragma unroll
        for (int t = 0; t < 8; t++) {
            float s = ssq[t];
            s += __shfl_xor_sync(0xffffffffu, s, 16);
            s += __shfl_xor_sync(0xffffffffu, s, 8);
            s += __shfl_xor_sync(0xffffffffu, s, 4);
            s += __shfl_xor_sync(0xffffffffu, s, 2);
            s += __shfl_xor_sync(0xffffffffu, s, 1);
            if (lane == t) sRinv[warp * 8 + t] = __frcp_rn(sqrtf(s) + 1.f);
        }
        __syncthreads();

        // ============ phase 2: tf32 MMA, 16 edges x 32 outs per warp ========
        float acc[4][4];
#pragma unroll
        for (int n = 0; n < 4; n++)
#pragma unroll
            for (int q = 0; q < 4; q++) acc[n][q] = 0.f;

        const uint32_t* aB = sRad + (eh + g) * KP + tig;
        const uint32_t* bB = sW + tig * WOP + oh + g;

#pragma unroll 2
        for (int kc = 0; kc < KCH; kc++) {
            int k0 = kc * 8;
            uint32_t A0 = aB[k0];
            uint32_t A1 = aB[8 * KP + k0];
            uint32_t A2 = aB[k0 + 4];
            uint32_t A3 = aB[8 * KP + k0 + 4];
            uint32_t B[4][2];
#pragma unroll
            for (int n = 0; n < 4; n++) {
                B[n][0] = bB[k0 * WOP + n * 8];
                B[n][1] = bB[(k0 + 4) * WOP + n * 8];
            }
#pragma unroll
            for (int n = 0; n < 4; n++)
                mma8(acc[n][0], acc[n][1], acc[n][2], acc[n][3],
                     A0, A1, A2, A3, B[n][0], B[n][1]);
        }

        // ============ epilogue: (acc + b) * rinv -> scalar atomics ==========
        {
            int el0 = eh + g, el1 = eh + 8 + g;
            bool v0 = (tile * TILE_E + el0) < E;
            bool v1 = (tile * TILE_E + el1) < E;
            float ri0 = sRinv[el0], ri1 = sRinv[el1];
            float* ob0 = out + sRow[el0] * OSTRIDE;
            float* ob1 = out + sRow[el1] * OSTRIDE;
#pragma unroll
            for (int n = 0; n < 4; n++) {
                int o = oh + n * 8 + 2 * tig;
                float bo0 = sBias[o], bo1 = sBias[o + 1];
                if (v0) {
                    atomicAdd(ob0 + o,     (acc[n][0] + bo0) * ri0);
                    atomicAdd(ob0 + o + 1, (acc[n][1] + bo1) * ri0);
                }
                if (v1) {
                    atomicAdd(ob1 + o,     (acc[n][2] + bo0) * ri1);
                    atomicAdd(ob1 + o + 1, (acc[n][3] + bo1) * ri1);
                }
            }
        }
        __syncthreads();   // protect rad/rinv/row before next tile's phase 1
    }
}

// ---------------------------------------------------------------------------
__global__ void finalize_kernel(float* out, int n) {
    int v = blockIdx.x * blockDim.x + threadIdx.x;
    if (v >= n) return;
    float cf = 1.f / fmaxf(g_cnt[v], 1.f);
    float* p = out + v * OSTRIDE + 64;
#pragma unroll
    for (int d = 0; d < 12; d++) p[d] *= cf;
}

// ---------------------------------------------------------------------------
extern "C" void kernel_launch(void* const* d_in, const int* in_sizes, int n_in,
                              void* d_out, int out_size) {
    const float* coord = (const float*)d_in[0];
    const float* attr  = (const float*)d_in[1];
    const float* cw    = (const float*)d_in[2];
    const float* W     = (const float*)d_in[3];
    const float* bias  = (const float*)d_in[4];
    const int*   row   = (const int*)d_in[5];
    const int*   col   = (const int*)d_in[6];
    float* out = (float*)d_out;

    int N = in_sizes[2] / 4;
    int E = in_sizes[5];

    int smem_bytes = SMEM_FLOATS * sizeof(float);   // 230144
    cudaFuncSetAttribute(edge_kernel, cudaFuncAttributeMaxDynamicSharedMemorySize,
                         smem_bytes);

    zero_kernel<<<512, 256>>>(out, out_size, N);
    node_kernel<<<(N + 255) / 256, 256>>>(coord, cw, N);
    edge_kernel<<<148, 512, smem_bytes>>>(coord, attr, cw, W, bias, row, col, out, E);
    finalize_kernel<<<(N + 255) / 256, 256>>>(out, N);
}

// round 6
// speedup vs baseline: 1.7687x; 1.1349x over previous
#include <cuda_runtime.h>
#include <math.h>
#include <stdint.h>

#define NMAX 50000
#define DOUT 64
#define OSTRIDE 76
#define KCH 34            // 34 k-chunks of 8 -> K = 272 (265 real + 7 zero pad)
#define KP 276            // rad row stride (bank-conflict-free: 276 % 32 = 20)
#define WOP 72            // sW row stride (bank-conflict-free)

// shared memory offsets (floats)
#define OFF_W 0                     // 272*72       = 19584
#define OFF_RAD 19584               // 128*276      = 35328 -> 54912
#define OFF_ATT 54912               // 16 warps*128 =  2048 -> 56960
#define OFF_M 56960                 // 16 warps*16  =   256 -> 57216
#define OFF_RINV 57216              // 128 -> 57344
#define OFF_ROW 57344               // 128 -> 57472
#define OFF_BIAS 57472              // 64  -> 57536
#define SMEM_FLOATS 57536           // *4 = 230144 bytes

__device__ float g_lf[NMAX * 9];
__device__ float g_pooled[NMAX * 3];
__device__ float g_cnt[NMAX];

// ---------------------------------------------------------------------------
__global__ void zero_kernel(float* out, int out_n, int n_nodes) {
    int i = blockIdx.x * blockDim.x + threadIdx.x;
    int stride = gridDim.x * blockDim.x;
    for (int k = i; k < out_n; k += stride) out[k] = 0.f;
    for (int k = i; k < n_nodes; k += stride) g_cnt[k] = 0.f;
}

// ---------------------------------------------------------------------------
__global__ void node_kernel(const float* __restrict__ coord,
                            const float* __restrict__ cw, int n) {
    int v = blockIdx.x * blockDim.x + threadIdx.x;
    if (v >= n) return;
    const float* cp = coord + v * 12;
    float cax = cp[0], cay = cp[1], caz = cp[2];
    float ccx = cp[3], ccy = cp[4], ccz = cp[5];
    float nnx = cp[6], nny = cp[7], nnz = cp[8];

    float xx = ccx - cax, xy = ccy - cay, xz = ccz - caz;
    float xn = sqrtf(xx * xx + xy * xy + xz * xz) + 1e-8f;
    xx /= xn; xy /= xn; xz /= xn;

    float tx = nnx - cax, ty = nny - cay, tz = nnz - caz;
    float d = tx * xx + ty * xy + tz * xz;
    float yx = tx - d * xx, yy = ty - d * xy, yz = tz - d * xz;
    float yn = sqrtf(yx * yx + yy * yy + yz * yz) + 1e-8f;
    yx /= yn; yy /= yn; yz /= yn;

    float zx = xy * yz - xz * yy;
    float zy = xz * yx - xx * yz;
    float zz = xx * yy - xy * yx;

    float* L = g_lf + v * 9;
    L[0] = xx; L[1] = yx; L[2] = zx;
    L[3] = xy; L[4] = yy; L[5] = zy;
    L[6] = xz; L[7] = yz; L[8] = zz;

    float px = 0.f, py = 0.f, pz = 0.f, cs = 0.f;
#pragma unroll
    for (int i = 0; i < 4; i++) {
        float m = (cw[v * 4 + i] != 0.f) ? 1.f : 0.f;
        cs += m;
        px += cp[i * 3 + 0] * m;
        py += cp[i * 3 + 1] * m;
        pz += cp[i * 3 + 2] * m;
    }
    g_pooled[v * 3 + 0] = px / cs;
    g_pooled[v * 3 + 1] = py / cs;
    g_pooled[v * 3 + 2] = pz / cs;
}

// ---------------------------------------------------------------------------
__device__ __forceinline__ uint32_t f2tf(float f) {
    uint32_t u;
    asm("cvt.rna.tf32.f32 %0, %1;" : "=r"(u) : "f"(f));
    return u;
}

__device__ __forceinline__ void mma8(float& d0, float& d1, float& d2, float& d3,
                                     uint32_t a0, uint32_t a1, uint32_t a2, uint32_t a3,
                                     uint32_t b0, uint32_t b1) {
    asm volatile("mma.sync.aligned.m16n8k8.row.col.f32.tf32.tf32.f32 "
                 "{%0,%1,%2,%3}, {%4,%5,%6,%7}, {%8,%9}, {%0,%1,%2,%3};"
                 : "+f"(d0), "+f"(d1), "+f"(d2), "+f"(d3)
                 : "r"(a0), "r"(a1), "r"(a2), "r"(a3), "r"(b0), "r"(b1));
}

__device__ __forceinline__ void pair_bar(int pair) {
    asm volatile("bar.sync %0, 64;" :: "r"(pair + 1) : "memory");
}

// ---------------------------------------------------------------------------
// 8 independent 2-warp pipelines per CTA. Each pair owns a private 16-row rad
// slice; sync via named barrier only (no CTA-wide sync in the main loop).
__global__ void __launch_bounds__(512, 1)
edge_kernel(const float* __restrict__ coord, const float* __restrict__ attr,
            const float* __restrict__ cw, const float* __restrict__ W,
            const float* __restrict__ bias, const int* __restrict__ row,
            const int* __restrict__ col, float* __restrict__ out, int E) {
    extern __shared__ float sm[];
    uint32_t* sW   = (uint32_t*)(sm + OFF_W);
    float* sBias = sm + OFF_BIAS;

    int tid = threadIdx.x, warp = tid >> 5, lane = tid & 31;

    // Stage W (tf32, transposed, geo-zero columns dropped) + bias. Once per CTA.
    for (int idx = tid; idx < 272 * 64; idx += 512) {
        int k = idx >> 6, o = idx & 63;
        float v = 0.f;
        if (k < 265) v = W[o * 273 + (k < 256 ? k : k + 8)];
        sW[k * WOP + o] = f2tf(v);
    }
    if (tid < 64) sBias[tid] = bias[tid];
    __syncthreads();

    const int pair = warp >> 1;         // 0..7
    const int win  = warp & 1;          // which warp in the pair
    const int g = lane >> 2, tig = lane & 3;
    const int b16 = lane & 15, half = lane >> 4;
    const int oh = win * 32;            // this warp's output-column half

    uint32_t* sRadP = (uint32_t*)(sm + OFF_RAD) + pair * 16 * KP;
    float* sRinvP = sm + OFF_RINV + pair * 16;
    int*   sRowP  = (int*)(sm + OFF_ROW) + pair * 16;
    float* sAttW  = sm + OFF_ATT + warp * 128;   // [attr_r(64) | attr_c(64)]
    float* sMW    = sm + OFF_M + warp * 16;
    const int mi = (lane >> 2) & 3, mj = lane & 3;

    int gpair  = blockIdx.x * 8 + pair;
    int npairs = gridDim.x * 8;
    int ngroups = (E + 15) >> 4;

    for (int grp = gpair; grp < ngroups; grp += npairs) {
        // wait until the partner warp finished reading rad of the previous group
        pair_bar(pair);

        // ================= phase 1: 8 edges per warp =================
        int e0g = grp * 16 + win * 8;
        int rc = 0;
        {
            int e = e0g + (lane & 7);
            if (e < E) rc = (lane < 16) ? row[e] : col[e];
        }
        if (lane < 8) sRowP[win * 8 + lane] = rc;

        float ssq[8];
#pragma unroll
        for (int h4 = 0; h4 < 2; h4++) {
            // ---- batched prefetch of 4 edges (MLP=4) ----
            float4 av[4];
            float gv[4], lfv[4], pv[4];
            int rr[4];
#pragma unroll
            for (int u = 0; u < 4; u++) {
                int t = h4 * 4 + u;
                int r = __shfl_sync(0xffffffffu, rc, t);
                int c = __shfl_sync(0xffffffffu, rc, 16 + t);
                rr[u] = r;
                int nn = (lane < 16) ? r : c;
                av[u] = __ldg((const float4*)(attr + nn * 64) + b16);
                const float* gp;
                if (lane < 12)      gp = coord + r * 12 + lane;
                else if (lane < 24) gp = coord + c * 12 + (lane - 12);
                else if (lane < 28) gp = cw + r * 4 + (lane - 24);
                else                gp = cw + c * 4 + (lane - 28);
                gv[u] = __ldg(gp);
                lfv[u] = (lane < 9)
                       ? g_lf[r * 9 + lane] + g_lf[c * 9 + lane] : 0.f;
                pv[u] = (lane < 12) ? g_pooled[c * 3 + lane % 3] : 0.f;
            }

            // ---- process the 4 edges ----
#pragma unroll
            for (int u = 0; u < 4; u++) {
                int t = h4 * 4 + u;
                ((float4*)sAttW)[lane] = av[u];

                float gvu = gv[u];
                float rx = __shfl_sync(0xffffffffu, gvu, 3 * mi);
                float ry = __shfl_sync(0xffffffffu, gvu, 3 * mi + 1);
                float rz = __shfl_sync(0xffffffffu, gvu, 3 * mi + 2);
                float cx = __shfl_sync(0xffffffffu, gvu, 12 + 3 * mj);
                float cy = __shfl_sync(0xffffffffu, gvu, 13 + 3 * mj);
                float cz = __shfl_sync(0xffffffffu, gvu, 14 + 3 * mj);
                float wr = __shfl_sync(0xffffffffu, gvu, 24 + mi);
                float wc = __shfl_sync(0xffffffffu, gvu, 28 + mj);
                if (lane < 16) {
                    float dx = rx - cx, dy = ry - cy, dz = rz - cz;
                    sMW[lane] = sqrtf(dx * dx + dy * dy + dz * dz) * wr * wc;
                }
                __syncwarp();

                const float* s_ac = sAttW + 64;
                float a0 = s_ac[b16], a1 = s_ac[16 + b16];
                float a2 = s_ac[32 + b16], a3 = s_ac[48 + b16];
                float tmp0 = sMW[0]  * a0 + sMW[1]  * a1 + sMW[2]  * a2 + sMW[3]  * a3;
                float tmp1 = sMW[4]  * a0 + sMW[5]  * a1 + sMW[6]  * a2 + sMW[7]  * a3;
                float tmp2 = sMW[8]  * a0 + sMW[9]  * a1 + sMW[10] * a2 + sMW[11] * a3;
                float tmp3 = sMW[12] * a0 + sMW[13] * a1 + sMW[14] * a2 + sMW[15] * a3;

                uint32_t* rrow = sRadP + (win * 8 + t) * KP;
                float part = 0.f;
#pragma unroll
                for (int s = 0; s < 8; s++) {
                    int a = half * 8 + s;
                    float v = sAttW[a] * tmp0 + sAttW[16 + a] * tmp1
                            + sAttW[32 + a] * tmp2 + sAttW[48 + a] * tmp3;
                    rrow[a * 16 + b16] = f2tf(v);
                    part += v * v;
                }
                if (lane < 9) {
                    rrow[256 + lane] = f2tf(lfv[u]);
                    part += lfv[u] * lfv[u];
                } else if (lane < 20) {
                    rrow[256 + lane] = 0u;   // k = 265..275 zero pad
                }
                ssq[t] = part;

                // coord aggregation + count (fire-and-forget REDG)
                if (e0g + t < E) {
                    if (lane < 12)
                        atomicAdd(out + rr[u] * OSTRIDE + 64 + lane, gvu - pv[u]);
                    else if (lane == 12)
                        atomicAdd(&g_cnt[rr[u]], 1.f);
                }
                __syncwarp();
            }
        }

        // deferred reductions: 8 independent shuffle trees, pipelined
#pragma unroll
        for (int t = 0; t < 8; t++) {
            float s = ssq[t];
            s += __shfl_xor_sync(0xffffffffu, s, 16);
            s += __shfl_xor_sync(0xffffffffu, s, 8);
            s += __shfl_xor_sync(0xffffffffu, s, 4);
            s += __shfl_xor_sync(0xffffffffu, s, 2);
            s += __shfl_xor_sync(0xffffffffu, s, 1);
            if (lane == t) sRinvP[win * 8 + t] = __frcp_rn(sqrtf(s) + 1.f);
        }
        pair_bar(pair);   // rad/rinv/row of both warps visible to the pair

        // ===== phase 2: tf32 MMA, 16 edges x 32 outs per warp (pair's rad) ==
        float acc[4][4];
#pragma unroll
        for (int n = 0; n < 4; n++)
#pragma unroll
            for (int q = 0; q < 4; q++) acc[n][q] = 0.f;

        const uint32_t* aB = sRadP + g * KP + tig;
        const uint32_t* bB = sW + tig * WOP + oh + g;

#pragma unroll 2
        for (int kc = 0; kc < KCH; kc++) {
            int k0 = kc * 8;
            uint32_t A0 = aB[k0];
            uint32_t A1 = aB[8 * KP + k0];
            uint32_t A2 = aB[k0 + 4];
            uint32_t A3 = aB[8 * KP + k0 + 4];
            uint32_t B[4][2];
#pragma unroll
            for (int n = 0; n < 4; n++) {
                B[n][0] = bB[k0 * WOP + n * 8];
                B[n][1] = bB[(k0 + 4) * WOP + n * 8];
            }
#pragma unroll
            for (int n = 0; n < 4; n++)
                mma8(acc[n][0], acc[n][1], acc[n][2], acc[n][3],
                     A0, A1, A2, A3, B[n][0], B[n][1]);
        }

        // ============ epilogue: (acc + b) * rinv -> scalar atomics ==========
        {
            int el0 = g, el1 = 8 + g;
            bool v0 = (grp * 16 + el0) < E;
            bool v1 = (grp * 16 + el1) < E;
            float ri0 = sRinvP[el0], ri1 = sRinvP[el1];
            float* ob0 = out + sRowP[el0] * OSTRIDE;
            float* ob1 = out + sRowP[el1] * OSTRIDE;
#pragma unroll
            for (int n = 0; n < 4; n++) {
                int o = oh + n * 8 + 2 * tig;
                float bo0 = sBias[o], bo1 = sBias[o + 1];
                if (v0) {
                    atomicAdd(ob0 + o,     (acc[n][0] + bo0) * ri0);
                    atomicAdd(ob0 + o + 1, (acc[n][1] + bo1) * ri0);
                }
                if (v1) {
                    atomicAdd(ob1 + o,     (acc[n][2] + bo0) * ri1);
                    atomicAdd(ob1 + o + 1, (acc[n][3] + bo1) * ri1);
                }
            }
        }
    }
}

// ---------------------------------------------------------------------------
__global__ void finalize_kernel(float* out, int n) {
    int v = blockIdx.x * blockDim.x + threadIdx.x;
    if (v >= n) return;
    float cf = 1.f / fmaxf(g_cnt[v], 1.f);
    float* p = out + v * OSTRIDE + 64;
#pragma unroll
    for (int d = 0; d < 12; d++) p[d] *= cf;
}

// ---------------------------------------------------------------------------
extern "C" void kernel_launch(void* const* d_in, const int* in_sizes, int n_in,
                              void* d_out, int out_size) {
    const float* coord = (const float*)d_in[0];
    const float* attr  = (const float*)d_in[1];
    const float* cw    = (const float*)d_in[2];
    const float* W     = (const float*)d_in[3];
    const float* bias  = (const float*)d_in[4];
    const int*   row   = (const int*)d_in[5];
    const int*   col   = (const int*)d_in[6];
    float* out = (float*)d_out;

    int N = in_sizes[2] / 4;
    int E = in_sizes[5];

    int smem_bytes = SMEM_FLOATS * sizeof(float);   // 230144
    cudaFuncSetAttribute(edge_kernel, cudaFuncAttributeMaxDynamicSharedMemorySize,
                         smem_bytes);

    zero_kernel<<<512, 256>>>(out, out_size, N);
    node_kernel<<<(N + 255) / 256, 256>>>(coord, cw, N);
    edge_kernel<<<148, 512, smem_bytes>>>(coord, attr, cw, W, bias, row, col, out, E);
    finalize_kernel<<<(N + 255) / 256, 256>>>(out, N);
}

// round 7
// speedup vs baseline: 2.0598x; 1.1646x over previous
#include <cuda_runtime.h>
#include <cuda_fp16.h>
#include <math.h>
#include <stdint.h>

#define NMAX 50000
#define DOUT 64
#define OSTRIDE 76
#define KCH16 17          // 17 k-chunks of 16 -> K = 272 (265 real + 7 zero pad)
#define KWH 148           // rad/W row stride in 32-bit words (296 halves); 148%32=20
#define NWARP 20
#define NPAIR 10

// shared memory offsets (32-bit words)
#define OFF_W 0                     // 64*148       = 9472
#define OFF_RAD 9472                // 160*148      = 23680 -> 33152
#define OFF_ATT 33152               // 20 warps*256 =  5120 -> 38272 (double-buffered)
#define OFF_M 38272                 // 20 warps*32  =   640 -> 38912 (double-buffered)
#define OFF_RINV 38912              // 160 -> 39072
#define OFF_ROW 39072               // 160 -> 39232
#define OFF_BIAS 39232              // 64  -> 39296
#define SMEM_WORDS 39296            // *4 = 157184 bytes

__device__ float g_lf[NMAX * 9];
__device__ float g_pooled[NMAX * 3];
__device__ float g_cnt[NMAX];

// ---------------------------------------------------------------------------
__global__ void zero_kernel(float* out, int out_n, int n_nodes) {
    int i = blockIdx.x * blockDim.x + threadIdx.x;
    int stride = gridDim.x * blockDim.x;
    for (int k = i; k < out_n; k += stride) out[k] = 0.f;
    for (int k = i; k < n_nodes; k += stride) g_cnt[k] = 0.f;
}

// ---------------------------------------------------------------------------
__global__ void node_kernel(const float* __restrict__ coord,
                            const float* __restrict__ cw, int n) {
    int v = blockIdx.x * blockDim.x + threadIdx.x;
    if (v >= n) return;
    const float* cp = coord + v * 12;
    float cax = cp[0], cay = cp[1], caz = cp[2];
    float ccx = cp[3], ccy = cp[4], ccz = cp[5];
    float nnx = cp[6], nny = cp[7], nnz = cp[8];

    float xx = ccx - cax, xy = ccy - cay, xz = ccz - caz;
    float xn = sqrtf(xx * xx + xy * xy + xz * xz) + 1e-8f;
    xx /= xn; xy /= xn; xz /= xn;

    float tx = nnx - cax, ty = nny - cay, tz = nnz - caz;
    float d = tx * xx + ty * xy + tz * xz;
    float yx = tx - d * xx, yy = ty - d * xy, yz = tz - d * xz;
    float yn = sqrtf(yx * yx + yy * yy + yz * yz) + 1e-8f;
    yx /= yn; yy /= yn; yz /= yn;

    float zx = xy * yz - xz * yy;
    float zy = xz * yx - xx * yz;
    float zz = xx * yy - xy * yx;

    float* L = g_lf + v * 9;
    L[0] = xx; L[1] = yx; L[2] = zx;
    L[3] = xy; L[4] = yy; L[5] = zy;
    L[6] = xz; L[7] = yz; L[8] = zz;

    float px = 0.f, py = 0.f, pz = 0.f, cs = 0.f;
#pragma unroll
    for (int i = 0; i < 4; i++) {
        float m = (cw[v * 4 + i] != 0.f) ? 1.f : 0.f;
        cs += m;
        px += cp[i * 3 + 0] * m;
        py += cp[i * 3 + 1] * m;
        pz += cp[i * 3 + 2] * m;
    }
    g_pooled[v * 3 + 0] = px / cs;
    g_pooled[v * 3 + 1] = py / cs;
    g_pooled[v * 3 + 2] = pz / cs;
}

// ---------------------------------------------------------------------------
__device__ __forceinline__ void mma16(float& d0, float& d1, float& d2, float& d3,
                                      uint32_t a0, uint32_t a1, uint32_t a2, uint32_t a3,
                                      uint32_t b0, uint32_t b1) {
    asm volatile("mma.sync.aligned.m16n8k16.row.col.f32.f16.f16.f32 "
                 "{%0,%1,%2,%3}, {%4,%5,%6,%7}, {%8,%9}, {%0,%1,%2,%3};"
                 : "+f"(d0), "+f"(d1), "+f"(d2), "+f"(d3)
                 : "r"(a0), "r"(a1), "r"(a2), "r"(a3), "r"(b0), "r"(b1));
}

__device__ __forceinline__ void pair_bar(int pair) {
    asm volatile("bar.sync %0, 64;" :: "r"(pair + 1) : "memory");
}

// ---------------------------------------------------------------------------
// 10 independent 2-warp pipelines per CTA; fp16 GEMM operands, fp32 accum.
__global__ void __launch_bounds__(640, 1)
edge_kernel(const float* __restrict__ coord, const float* __restrict__ attr,
            const float* __restrict__ cw, const float* __restrict__ W,
            const float* __restrict__ bias, const int* __restrict__ row,
            const int* __restrict__ col, float* __restrict__ out, int E) {
    extern __shared__ float sm[];
    uint32_t* sWw  = (uint32_t*)(sm + OFF_W);      // W fp16: [o][kword], stride KWH
    __half*   sRadH = (__half*)(sm + OFF_RAD);     // rad fp16: rows of 296 halves
    float* sBias = sm + OFF_BIAS;

    int tid = threadIdx.x, warp = tid >> 5, lane = tid & 31;

    // Stage W (fp16 pairs, [o][k] layout, geo-zero cols dropped, K padded to 272)
    for (int idx = tid; idx < 64 * 136; idx += 640) {
        int o = idx / 136, kw = idx % 136;
        int k0 = 2 * kw, k1 = 2 * kw + 1;
        float f0 = (k0 < 265) ? W[o * 273 + (k0 < 256 ? k0 : k0 + 8)] : 0.f;
        float f1 = (k1 < 265) ? W[o * 273 + (k1 < 256 ? k1 : k1 + 8)] : 0.f;
        __half2 h = __floats2half2_rn(f0, f1);
        sWw[o * KWH + kw] = *(uint32_t*)&h;
    }
    for (int idx = tid; idx < 64 * 12; idx += 640) {   // pad words 136..147
        int o = idx / 12, kw = 136 + idx % 12;
        sWw[o * KWH + kw] = 0u;
    }
    if (tid < 64) sBias[tid] = bias[tid];
    __syncthreads();

    const int pair = warp >> 1;         // 0..9
    const int win  = warp & 1;
    const int g = lane >> 2, tig = lane & 3;
    const int b16 = lane & 15, half = lane >> 4;
    const int oh = win * 32;            // this warp's output-column half

    uint32_t* radw   = (uint32_t*)(sm + OFF_RAD) + pair * 16 * KWH;
    __half*   sRadP  = sRadH + pair * 16 * 296;
    float* sRinvP = sm + OFF_RINV + pair * 16;
    int*   sRowP  = (int*)(sm + OFF_ROW) + pair * 16;
    float* sAttW  = sm + OFF_ATT + warp * 256;   // 2 slots x [attr_r(64)|attr_c(64)]
    float* sMW    = sm + OFF_M + warp * 32;      // 2 slots x 16
    const int mi = (lane >> 2) & 3, mj = lane & 3;

    int gpair  = blockIdx.x * NPAIR + pair;
    int npairs = gridDim.x * NPAIR;
    int ngroups = (E + 15) >> 4;

    for (int grp = gpair; grp < ngroups; grp += npairs) {
        // wait until the partner warp finished reading rad of the previous group
        pair_bar(pair);

        // ================= phase 1: 8 edges per warp =================
        int e0g = grp * 16 + win * 8;
        int rc = 0;
        {
            int e = e0g + (lane & 7);
            if (e < E) rc = (lane < 16) ? row[e] : col[e];
        }
        if (lane < 8) sRowP[win * 8 + lane] = rc;

        float ssq[8];
#pragma unroll
        for (int h4 = 0; h4 < 2; h4++) {
            // ---- batched prefetch of 4 edges (MLP=4) ----
            float4 av[4];
            float gv[4], lfv[4], pv[4];
            int rr[4];
#pragma unroll
            for (int u = 0; u < 4; u++) {
                int t = h4 * 4 + u;
                int r = __shfl_sync(0xffffffffu, rc, t);
                int c = __shfl_sync(0xffffffffu, rc, 16 + t);
                rr[u] = r;
                int nn = (lane < 16) ? r : c;
                av[u] = __ldg((const float4*)(attr + nn * 64) + b16);
                const float* gp;
                if (lane < 12)      gp = coord + r * 12 + lane;
                else if (lane < 24) gp = coord + c * 12 + (lane - 12);
                else if (lane < 28) gp = cw + r * 4 + (lane - 24);
                else                gp = cw + c * 4 + (lane - 28);
                gv[u] = __ldg(gp);
                lfv[u] = (lane < 9)
                       ? g_lf[r * 9 + lane] + g_lf[c * 9 + lane] : 0.f;
                pv[u] = (lane < 12) ? g_pooled[c * 3 + lane % 3] : 0.f;
            }

            // ---- process the 4 edges (double-buffered staging) ----
#pragma unroll
            for (int u = 0; u < 4; u++) {
                int t = h4 * 4 + u;
                float* slot = sAttW + (t & 1) * 128;
                float* sMs  = sMW + (t & 1) * 16;
                ((float4*)slot)[lane] = av[u];

                float gvu = gv[u];
                float rx = __shfl_sync(0xffffffffu, gvu, 3 * mi);
                float ry = __shfl_sync(0xffffffffu, gvu, 3 * mi + 1);
                float rz = __shfl_sync(0xffffffffu, gvu, 3 * mi + 2);
                float cx = __shfl_sync(0xffffffffu, gvu, 12 + 3 * mj);
                float cy = __shfl_sync(0xffffffffu, gvu, 13 + 3 * mj);
                float cz = __shfl_sync(0xffffffffu, gvu, 14 + 3 * mj);
                float wr = __shfl_sync(0xffffffffu, gvu, 24 + mi);
                float wc = __shfl_sync(0xffffffffu, gvu, 28 + mj);
                if (lane < 16) {
                    float dx = rx - cx, dy = ry - cy, dz = rz - cz;
                    sMs[lane] = sqrtf(dx * dx + dy * dy + dz * dz) * wr * wc;
                }
                __syncwarp();

                const float* s_ac = slot + 64;
                float a0 = s_ac[b16], a1 = s_ac[16 + b16];
                float a2 = s_ac[32 + b16], a3 = s_ac[48 + b16];
                float tmp0 = sMs[0]  * a0 + sMs[1]  * a1 + sMs[2]  * a2 + sMs[3]  * a3;
                float tmp1 = sMs[4]  * a0 + sMs[5]  * a1 + sMs[6]  * a2 + sMs[7]  * a3;
                float tmp2 = sMs[8]  * a0 + sMs[9]  * a1 + sMs[10] * a2 + sMs[11] * a3;
                float tmp3 = sMs[12] * a0 + sMs[13] * a1 + sMs[14] * a2 + sMs[15] * a3;

                __half* rrow = sRadP + (win * 8 + t) * 296;
                float part = 0.f;
#pragma unroll
                for (int s = 0; s < 8; s++) {
                    int a = half * 8 + s;
                    float v = slot[a] * tmp0 + slot[16 + a] * tmp1
                            + slot[32 + a] * tmp2 + slot[48 + a] * tmp3;
                    rrow[a * 16 + b16] = __float2half_rn(v);
                    part += v * v;
                }
                if (lane < 9) {
                    rrow[256 + lane] = __float2half_rn(lfv[u]);
                    part += lfv[u] * lfv[u];
                }
                if (lane < 31) rrow[265 + lane] = __ushort_as_half(0);  // pad
                ssq[t] = part;

                // coord aggregation + count (fire-and-forget REDG)
                if (e0g + t < E) {
                    if (lane < 12)
                        atomicAdd(out + rr[u] * OSTRIDE + 64 + lane, gvu - pv[u]);
                    else if (lane == 12)
                        atomicAdd(&g_cnt[rr[u]], 1.f);
                }
            }
        }

        // deferred reductions: 8 independent shuffle trees, pipelined
#pragma unroll
        for (int t = 0; t < 8; t++) {
            float s = ssq[t];
            s += __shfl_xor_sync(0xffffffffu, s, 16);
            s += __shfl_xor_sync(0xffffffffu, s, 8);
            s += __shfl_xor_sync(0xffffffffu, s, 4);
            s += __shfl_xor_sync(0xffffffffu, s, 2);
            s += __shfl_xor_sync(0xffffffffu, s, 1);
            if (lane == t) sRinvP[win * 8 + t] = __frcp_rn(sqrtf(s) + 1.f);
        }
        pair_bar(pair);   // rad/rinv/row of both warps visible to the pair

        // ===== phase 2: fp16 MMA (m16n8k16), 16 edges x 32 outs per warp ====
        float acc[4][4];
#pragma unroll
        for (int n = 0; n < 4; n++)
#pragma unroll
            for (int q = 0; q < 4; q++) acc[n][q] = 0.f;

        const uint32_t* aB = radw + g * KWH + tig;
        const uint32_t* bB = sWw + (oh + g) * KWH + tig;

#pragma unroll 2
        for (int kc = 0; kc < KCH16; kc++) {
            int k0 = kc * 8;
            uint32_t A0 = aB[k0];
            uint32_t A1 = aB[8 * KWH + k0];
            uint32_t A2 = aB[k0 + 4];
            uint32_t A3 = aB[8 * KWH + k0 + 4];
            uint32_t B[4][2];
#pragma unroll
            for (int n = 0; n < 4; n++) {
                B[n][0] = bB[(n * 8) * KWH + k0];
                B[n][1] = bB[(n * 8) * KWH + k0 + 4];
            }
#pragma unroll
            for (int n = 0; n < 4; n++)
                mma16(acc[n][0], acc[n][1], acc[n][2], acc[n][3],
                      A0, A1, A2, A3, B[n][0], B[n][1]);
        }

        // ============ epilogue: (acc + b) * rinv -> scalar atomics ==========
        {
            int el0 = g, el1 = 8 + g;
            bool v0 = (grp * 16 + el0) < E;
            bool v1 = (grp * 16 + el1) < E;
            float ri0 = sRinvP[el0], ri1 = sRinvP[el1];
            float* ob0 = out + sRowP[el0] * OSTRIDE;
            float* ob1 = out + sRowP[el1] * OSTRIDE;
#pragma unroll
            for (int n = 0; n < 4; n++) {
                int o = oh + n * 8 + 2 * tig;
                float bo0 = sBias[o], bo1 = sBias[o + 1];
                if (v0) {
                    atomicAdd(ob0 + o,     (acc[n][0] + bo0) * ri0);
                    atomicAdd(ob0 + o + 1, (acc[n][1] + bo1) * ri0);
                }
                if (v1) {
                    atomicAdd(ob1 + o,     (acc[n][2] + bo0) * ri1);
                    atomicAdd(ob1 + o + 1, (acc[n][3] + bo1) * ri1);
                }
            }
        }
    }
}

// ---------------------------------------------------------------------------
__global__ void finalize_kernel(float* out, int n) {
    int v = blockIdx.x * blockDim.x + threadIdx.x;
    if (v >= n) return;
    float cf = 1.f / fmaxf(g_cnt[v], 1.f);
    float* p = out + v * OSTRIDE + 64;
#pragma unroll
    for (int d = 0; d < 12; d++) p[d] *= cf;
}

// ---------------------------------------------------------------------------
extern "C" void kernel_launch(void* const* d_in, const int* in_sizes, int n_in,
                              void* d_out, int out_size) {
    const float* coord = (const float*)d_in[0];
    const float* attr  = (const float*)d_in[1];
    const float* cw    = (const float*)d_in[2];
    const float* W     = (const float*)d_in[3];
    const float* bias  = (const float*)d_in[4];
    const int*   row   = (const int*)d_in[5];
    const int*   col   = (const int*)d_in[6];
    float* out = (float*)d_out;

    int N = in_sizes[2] / 4;
    int E = in_sizes[5];

    int smem_bytes = SMEM_WORDS * sizeof(float);   // 157184
    cudaFuncSetAttribute(edge_kernel, cudaFuncAttributeMaxDynamicSharedMemorySize,
                         smem_bytes);

    zero_kernel<<<512, 256>>>(out, out_size, N);
    node_kernel<<<(N + 255) / 256, 256>>>(coord, cw, N);
    edge_kernel<<<148, 640, smem_bytes>>>(coord, attr, cw, W, bias, row, col, out, E);
    finalize_kernel<<<(N + 255) / 256, 256>>>(out, N);
}